// round 1
// baseline (speedup 1.0000x reference)
#include <cuda_runtime.h>

// ---------------- problem constants (fixed by the dataset) ----------------
#define DI   128                 // model dim D
#define BATCH 2
#define HDm  64
#define WDm  96
#define HUm  128
#define WUm  192
#define SDL  (HDm*WDm)           // 6144  downsampled pixels per batch
#define SPL  (HUm*WUm)           // 24576 upsampled pixels per batch
#define ND   (BATCH*SDL)         // 12288
#define NP   (BATCH*SPL)         // 49152
#define KVP  640                 // kv0(256) | kv1(256) | ctxp(128)

// ---------------- device scratch (no allocations allowed) -----------------
__device__ float g_ctxln[ND*DI];        // LN(context pixel), row-major
__device__ float g_x[NP*DI];            // running x, row-major
__device__ float g_kvp[ND*KVP];         // precomputed kv/ctxp per dpixel
__device__ float g_W[DI*KVP];           // folded weights for dpixel GEMM
__device__ float g_bias[KVP];

// ========================================================================
// K1: fold nc_w/nc_b into combined weight  W[c][j], bias[j]
//   j in [0,256):   kv layer0     j in [256,512): kv layer1
//   j in [512,640): ctxp (wcf)
// ========================================================================
__global__ void prep_kernel(const float* __restrict__ nc_w,
                            const float* __restrict__ nc_b,
                            const float* __restrict__ wkv,
                            const float* __restrict__ bkv,
                            const float* __restrict__ wcf,
                            const float* __restrict__ bcf) {
    int j = blockIdx.x * blockDim.x + threadIdx.x;
    if (j >= KVP) return;
    if (j < 512) {
        int l  = j >> 8;
        int jj = j & 255;
        const float* w = wkv + (size_t)l * DI * 256;
        float bias = bkv[l*256 + jj];
        for (int c = 0; c < DI; c++) {
            float wv = w[c*256 + jj];
            g_W[c*KVP + j] = nc_w[l*DI + c] * wv;
            bias += nc_b[l*DI + c] * wv;
        }
        g_bias[j] = bias;
    } else {
        int jj = j - 512;
        for (int c = 0; c < DI; c++)
            g_W[c*KVP + j] = wcf[c*DI + jj];
        g_bias[j] = bcf[jj];
    }
}

// ========================================================================
// K2: transpose feat_map (B,D,Hd,Wd) -> per-dpixel rows + fused LayerNorm
// ========================================================================
__global__ void trln_kernel(const float* __restrict__ fm) {
    __shared__ float st[DI][33];
    int dp0 = blockIdx.x * 32;                // 32 | 6144 -> no batch straddle
    int b = dp0 / SDL, hw0 = dp0 % SDL;
    const float* src = fm + (size_t)b * DI * SDL + hw0;
    int t = threadIdx.x;
    #pragma unroll
    for (int i = 0; i < 16; i++) {
        int e = t + i*256;
        int c = e >> 5, p = e & 31;
        st[c][p] = src[(size_t)c*SDL + p];
    }
    __syncthreads();
    int p = t >> 3, g = t & 7;                // 8 threads per pixel
    float s = 0.f, s2 = 0.f;
    #pragma unroll
    for (int i = 0; i < 16; i++) {
        float v = st[g*16 + i][p];
        s += v; s2 += v*v;
    }
    #pragma unroll
    for (int off = 4; off; off >>= 1) {
        s  += __shfl_xor_sync(0xffffffffu, s,  off, 8);
        s2 += __shfl_xor_sync(0xffffffffu, s2, off, 8);
    }
    float mu   = s * (1.f/128.f);
    float rstd = rsqrtf(s2*(1.f/128.f) - mu*mu + 1e-6f);
    float* dst = g_ctxln + (size_t)(dp0 + p) * DI;
    #pragma unroll
    for (int i = 0; i < 16; i++) {
        int c = g*16 + i;
        dst[c] = (st[c][p] - mu) * rstd;
    }
}

// ========================================================================
// K3: transpose feat_map_up (B,D,Hu,Wu) -> x rows (no LN)
// ========================================================================
__global__ void trx_kernel(const float* __restrict__ fmu) {
    __shared__ float st[DI][33];
    int n0 = blockIdx.x * 32;
    int b = n0 / SPL, s0 = n0 % SPL;
    const float* src = fmu + (size_t)b * DI * SPL + s0;
    int t = threadIdx.x;
    #pragma unroll
    for (int i = 0; i < 16; i++) {
        int e = t + i*256;
        int c = e >> 5, p = e & 31;
        st[c][p] = src[(size_t)c*SPL + p];
    }
    __syncthreads();
    int p = t >> 3, g = t & 7;
    float* dst = g_x + (size_t)(n0 + p) * DI;
    #pragma unroll
    for (int i = 0; i < 16; i++) {
        int c = g*16 + i;
        dst[c] = st[c][p];
    }
}

// ------------------------- shared GEMM helpers ---------------------------
__device__ __forceinline__ void load_w128(float* sW, const float* __restrict__ src,
                                          int stride, int t) {
    #pragma unroll
    for (int i = 0; i < 16; i++) {
        int f = t + i*256;
        int k = f >> 5, j4 = f & 31;
        *(float4*)(sW + k*132 + j4*4) =
            __ldg((const float4*)(src + (size_t)k*stride + j4*4));
    }
}

// C(64x128) += A(64x128,pitch132) * W(128x128,pitch132); thread (ty,tx) does 4x8
__device__ __forceinline__ void gemm_tile(const float* __restrict__ sA,
                                          const float* __restrict__ sW,
                                          float acc[4][8], int rr, int cc) {
    #pragma unroll 2
    for (int k = 0; k < DI; k++) {
        float a0 = sA[(rr+0)*132 + k];
        float a1 = sA[(rr+1)*132 + k];
        float a2 = sA[(rr+2)*132 + k];
        float a3 = sA[(rr+3)*132 + k];
        float4 b0 = *(const float4*)(sW + k*132 + cc);
        float4 b1 = *(const float4*)(sW + k*132 + cc + 4);
        float bb[8] = {b0.x,b0.y,b0.z,b0.w,b1.x,b1.y,b1.z,b1.w};
        #pragma unroll
        for (int j = 0; j < 8; j++) {
            acc[0][j] = fmaf(a0, bb[j], acc[0][j]);
            acc[1][j] = fmaf(a1, bb[j], acc[1][j]);
            acc[2][j] = fmaf(a2, bb[j], acc[2][j]);
            acc[3][j] = fmaf(a3, bb[j], acc[3][j]);
        }
    }
}

// per-row LayerNorm on a 64x128 tile (pitch 132); 4 lanes per row
__device__ __forceinline__ void ln_tile(const float* sx, float* sA, int r, int g) {
    const float* row = sx + r*132 + g*32;
    float s = 0.f, s2 = 0.f;
    #pragma unroll
    for (int i = 0; i < 8; i++) {
        float4 v = *(const float4*)(row + i*4);
        s  += (v.x + v.y) + (v.z + v.w);
        s2 += (v.x*v.x + v.y*v.y) + (v.z*v.z + v.w*v.w);
    }
    s  += __shfl_xor_sync(0xffffffffu, s, 1, 4);
    s  += __shfl_xor_sync(0xffffffffu, s, 2, 4);
    s2 += __shfl_xor_sync(0xffffffffu, s2, 1, 4);
    s2 += __shfl_xor_sync(0xffffffffu, s2, 2, 4);
    float mu   = s * (1.f/128.f);
    float rstd = rsqrtf(s2*(1.f/128.f) - mu*mu + 1e-6f);
    float* dst = sA + r*132 + g*32;
    #pragma unroll
    for (int i = 0; i < 8; i++) {
        float4 v = *(const float4*)(row + i*4);
        float4 o;
        o.x = (v.x-mu)*rstd; o.y = (v.y-mu)*rstd;
        o.z = (v.z-mu)*rstd; o.w = (v.w-mu)*rstd;
        *(float4*)(dst + i*4) = o;
    }
}

__device__ __forceinline__ float gelu_tanh(float v) {
    float u = 0.7978845608028654f * (v + 0.044715f * v * v * v);
    u = fminf(fmaxf(u, -15.f), 15.f);
    float e = __expf(-2.f * u);
    float th = (1.f - e) / (1.f + e);
    return 0.5f * v * (1.f + th);
}

// ========================================================================
// K4: per-dpixel GEMM  g_kvp[12288,640] = g_ctxln[12288,128] @ g_W + g_bias
// ========================================================================
#define DGEMM_SMEM ((64*132 + 128*132) * 4)
__global__ void __launch_bounds__(256, 1) dgemm_kernel() {
    extern __shared__ float sm[];
    float* sA = sm;
    float* sW = sm + 64*132;
    int r0  = blockIdx.x * 64;
    int c0b = blockIdx.y * 128;
    int t = threadIdx.x;
    #pragma unroll
    for (int i = 0; i < 8; i++) {
        int f = t + i*256;
        int r = f >> 5, j4 = f & 31;
        *(float4*)(sA + r*132 + j4*4) =
            *(const float4*)(g_ctxln + (size_t)(r0 + r)*DI + j4*4);
    }
    #pragma unroll
    for (int i = 0; i < 16; i++) {
        int f = t + i*256;
        int k = f >> 5, j4 = f & 31;
        *(float4*)(sW + k*132 + j4*4) =
            *(const float4*)(g_W + (size_t)k*KVP + c0b + j4*4);
    }
    __syncthreads();
    int tx = t & 15, ty = t >> 4;
    int rr = ty*4, cc = tx*8;
    float acc[4][8] = {};
    gemm_tile(sA, sW, acc, rr, cc);
    #pragma unroll
    for (int i = 0; i < 4; i++) {
        float* dst = g_kvp + (size_t)(r0 + rr + i)*KVP + c0b + cc;
        float4 o0, o1;
        o0.x = acc[i][0] + g_bias[c0b+cc+0];
        o0.y = acc[i][1] + g_bias[c0b+cc+1];
        o0.z = acc[i][2] + g_bias[c0b+cc+2];
        o0.w = acc[i][3] + g_bias[c0b+cc+3];
        o1.x = acc[i][4] + g_bias[c0b+cc+4];
        o1.y = acc[i][5] + g_bias[c0b+cc+5];
        o1.z = acc[i][6] + g_bias[c0b+cc+6];
        o1.w = acc[i][7] + g_bias[c0b+cc+7];
        *(float4*)dst       = o0;
        *(float4*)(dst + 4) = o1;
    }
}

// ========================================================================
// K5: mega pixel kernel — 64 pixels/block, full 2-layer transformer + final
// ========================================================================
#define MEGA_SMEM ((3*64*132 + 128*132) * 4)
__global__ void __launch_bounds__(256, 1) mega_kernel(
    const float* __restrict__ wq,  const float* __restrict__ bq,
    const float* __restrict__ wo,  const float* __restrict__ bo,
    const float* __restrict__ w1,  const float* __restrict__ b1,
    const float* __restrict__ w2,  const float* __restrict__ b2,
    const float* __restrict__ wqf, const float* __restrict__ bqf,
    float* __restrict__ out)
{
    extern __shared__ float sm[];
    float* sx = sm;                  // raw x tile       64x132
    float* sA = sm + 64*132;         // LN(x) / q / o / xq
    float* sH = sm + 2*64*132;       // gelu(h) chunk / final probs
    float* sW = sm + 3*64*132;       // weight tile     128x132

    const int t  = threadIdx.x;
    const int n0 = blockIdx.x * 64;
    const int tx = t & 15, ty = t >> 4;
    const int rr = ty*4,   cc = tx*8;
    const int pp = t >> 2, hg = t & 3;   // attention: pixel, head

    // neighbor dpixel indices (edge-clamped 3x3 at half resolution)
    int dpix[9];
    {
        int n  = n0 + pp;
        int b  = n / SPL, s = n % SPL;
        int hu = s / WUm, wu = s % WUm;
        int hd = hu >> 1, wd = wu >> 1;
        #pragma unroll
        for (int i = 0; i < 3; i++)
            #pragma unroll
            for (int j = 0; j < 3; j++) {
                int hs = min(max(hd - 1 + i, 0), HDm - 1);
                int ws = min(max(wd - 1 + j, 0), WDm - 1);
                dpix[i*3 + j] = b*SDL + hs*WDm + ws;
            }
    }

    // load x tile
    #pragma unroll
    for (int i = 0; i < 8; i++) {
        int f = t + i*256;
        int r = f >> 5, j4 = f & 31;
        *(float4*)(sx + r*132 + j4*4) =
            *(const float4*)(g_x + (size_t)(n0 + r)*DI + j4*4);
    }
    __syncthreads();

    for (int l = 0; l < 2; l++) {
        // ---- q = LN(x) @ wq + bq ----
        ln_tile(sx, sA, pp, hg);
        load_w128(sW, wq + (size_t)l*DI*DI, DI, t);
        __syncthreads();
        {
            float acc[4][8] = {};
            gemm_tile(sA, sW, acc, rr, cc);
            __syncthreads();                      // all reads of sA done
            #pragma unroll
            for (int i = 0; i < 4; i++)
                #pragma unroll
                for (int j = 0; j < 8; j++)
                    sA[(rr+i)*132 + cc + j] = acc[i][j] + bq[l*DI + cc + j];
        }
        __syncthreads();

        // ---- attention: 1 thread per (pixel, head), 9 keys ----
        {
            float lo[9];
            float m = -1e30f;
            const float* qrow = sA + pp*132 + hg*32;
            #pragma unroll
            for (int kk = 0; kk < 9; kk++) {
                const float* kv = g_kvp + (size_t)dpix[kk]*KVP + l*256 + hg*32;
                float d = 0.f;
                #pragma unroll
                for (int i4 = 0; i4 < 8; i4++) {
                    float4 kvv = __ldg((const float4*)(kv + i4*4));
                    float4 qv  = *(const float4*)(qrow + i4*4);
                    d += qv.x*kvv.x + qv.y*kvv.y + qv.z*kvv.z + qv.w*kvv.w;
                }
                lo[kk] = d * 0.17677669529663687f;   // 1/sqrt(32)
                m = fmaxf(m, lo[kk]);
            }
            float ssum = 0.f;
            #pragma unroll
            for (int kk = 0; kk < 9; kk++) { lo[kk] = __expf(lo[kk] - m); ssum += lo[kk]; }
            float inv = 1.f / ssum;
            float4 o4[8] = {};
            #pragma unroll
            for (int kk = 0; kk < 9; kk++) {
                float w = lo[kk] * inv;
                const float* vv = g_kvp + (size_t)dpix[kk]*KVP + l*256 + 128 + hg*32;
                #pragma unroll
                for (int i4 = 0; i4 < 8; i4++) {
                    float4 v = __ldg((const float4*)(vv + i4*4));
                    o4[i4].x += w*v.x; o4[i4].y += w*v.y;
                    o4[i4].z += w*v.z; o4[i4].w += w*v.w;
                }
            }
            float* orow = sA + pp*132 + hg*32;       // own slice, no race
            #pragma unroll
            for (int i4 = 0; i4 < 8; i4++) *(float4*)(orow + i4*4) = o4[i4];
        }
        load_w128(sW, wo + (size_t)l*DI*DI, DI, t);
        __syncthreads();

        // ---- x += o @ wo + bo ----
        {
            float acc[4][8] = {};
            gemm_tile(sA, sW, acc, rr, cc);
            #pragma unroll
            for (int i = 0; i < 4; i++)
                #pragma unroll
                for (int j = 0; j < 8; j++)
                    sx[(rr+i)*132 + cc + j] += acc[i][j] + bo[l*DI + cc + j];
        }
        __syncthreads();

        // ---- MLP: x += gelu(LN(x)@w1+b1) @ w2 + b2, chunked over 512 ----
        ln_tile(sx, sA, pp, hg);
        float accX[4][8] = {};
        for (int c4 = 0; c4 < 4; c4++) {
            load_w128(sW, w1 + (size_t)l*DI*512 + c4*128, 512, t);
            __syncthreads();                       // sA + w1 ready, prev reads done
            {
                float acc[4][8] = {};
                gemm_tile(sA, sW, acc, rr, cc);
                #pragma unroll
                for (int i = 0; i < 4; i++)
                    #pragma unroll
                    for (int j = 0; j < 8; j++) {
                        float v = acc[i][j] + b1[l*512 + c4*128 + cc + j];
                        sH[(rr+i)*132 + cc + j] = gelu_tanh(v);
                    }
            }
            __syncthreads();                       // sH ready, w1 reads done
            load_w128(sW, w2 + (size_t)l*512*DI + (size_t)c4*128*DI, DI, t);
            __syncthreads();                       // w2 ready
            gemm_tile(sH, sW, accX, rr, cc);
            __syncthreads();                       // w2/sH reads done
        }
        #pragma unroll
        for (int i = 0; i < 4; i++)
            #pragma unroll
            for (int j = 0; j < 8; j++)
                sx[(rr+i)*132 + cc + j] += accX[i][j] + b2[l*DI + cc + j];
        __syncthreads();
    }

    // ---- final: xq = LN(x) @ wqf + bqf ----
    ln_tile(sx, sA, pp, hg);
    load_w128(sW, wqf, DI, t);
    __syncthreads();
    {
        float acc[4][8] = {};
        gemm_tile(sA, sW, acc, rr, cc);
        __syncthreads();
        #pragma unroll
        for (int i = 0; i < 4; i++)
            #pragma unroll
            for (int j = 0; j < 8; j++)
                sA[(rr+i)*132 + cc + j] = acc[i][j] + bqf[cc + j];
    }
    __syncthreads();

    // ---- logits = xq . ctxp / sqrt(128), softmax over 9 ----
    {
        float lo[9];
        const float* qrow = sA + pp*132 + hg*32;
        #pragma unroll
        for (int kk = 0; kk < 9; kk++) {
            const float* cp = g_kvp + (size_t)dpix[kk]*KVP + 512 + hg*32;
            float d = 0.f;
            #pragma unroll
            for (int i4 = 0; i4 < 8; i4++) {
                float4 c = __ldg((const float4*)(cp + i4*4));
                float4 q = *(const float4*)(qrow + i4*4);
                d += q.x*c.x + q.y*c.y + q.z*c.z + q.w*c.w;
            }
            lo[kk] = d;
        }
        #pragma unroll
        for (int kk = 0; kk < 9; kk++) {
            lo[kk] += __shfl_xor_sync(0xffffffffu, lo[kk], 1, 4);
            lo[kk] += __shfl_xor_sync(0xffffffffu, lo[kk], 2, 4);
            lo[kk] *= 0.08838834764831845f;       // 1/sqrt(128)
        }
        float m = -1e30f;
        #pragma unroll
        for (int kk = 0; kk < 9; kk++) m = fmaxf(m, lo[kk]);
        float ssum = 0.f;
        #pragma unroll
        for (int kk = 0; kk < 9; kk++) { lo[kk] = __expf(lo[kk] - m); ssum += lo[kk]; }
        float inv = 1.f / ssum;
        if (hg == 0) {
            #pragma unroll
            for (int kk = 0; kk < 9; kk++)
                sH[pp*132 + kk] = lo[kk] * inv;
        }
    }
    __syncthreads();

    // ---- coalesced output write: out[b][kk][hu][wu] ----
    {
        int b = n0 / SPL, s0 = n0 % SPL;
        #pragma unroll
        for (int i = 0; i < 3; i++) {
            int idx = t + i*256;
            if (idx < 576) {
                int kk = idx / 64, p = idx % 64;
                out[(size_t)b*9*SPL + (size_t)kk*SPL + s0 + p] = sH[p*132 + kk];
            }
        }
    }
}

// ========================================================================
extern "C" void kernel_launch(void* const* d_in, const int* in_sizes, int n_in,
                              void* d_out, int out_size) {
    const float* feat_map    = (const float*)d_in[0];
    const float* feat_map_up = (const float*)d_in[1];
    const float* nc_w = (const float*)d_in[2];
    const float* nc_b = (const float*)d_in[3];
    const float* wq   = (const float*)d_in[4];
    const float* bq   = (const float*)d_in[5];
    const float* wkv  = (const float*)d_in[6];
    const float* bkv  = (const float*)d_in[7];
    const float* wo   = (const float*)d_in[8];
    const float* bo   = (const float*)d_in[9];
    const float* w1   = (const float*)d_in[10];
    const float* b1   = (const float*)d_in[11];
    const float* w2   = (const float*)d_in[12];
    const float* b2   = (const float*)d_in[13];
    const float* wqf  = (const float*)d_in[14];
    const float* bqf  = (const float*)d_in[15];
    const float* wcf  = (const float*)d_in[16];
    const float* bcf  = (const float*)d_in[17];
    float* out = (float*)d_out;

    cudaFuncSetAttribute(dgemm_kernel,
                         cudaFuncAttributeMaxDynamicSharedMemorySize, DGEMM_SMEM);
    cudaFuncSetAttribute(mega_kernel,
                         cudaFuncAttributeMaxDynamicSharedMemorySize, MEGA_SMEM);

    prep_kernel<<<3, 256>>>(nc_w, nc_b, wkv, bkv, wcf, bcf);
    trln_kernel<<<ND/32, 256>>>(feat_map);
    trx_kernel<<<NP/32, 256>>>(feat_map_up);
    dgemm_kernel<<<dim3(ND/64, 5), 256, DGEMM_SMEM>>>();
    mega_kernel<<<NP/64, 256, MEGA_SMEM>>>(wq, bq, wo, bo, w1, b1, w2, b2,
                                           wqf, bqf, out);
}

// round 2
// speedup vs baseline: 1.2177x; 1.2177x over previous
#include <cuda_runtime.h>

// ---------------- problem constants (fixed by the dataset) ----------------
#define DI   128
#define BATCH 2
#define HDm  64
#define WDm  96
#define HUm  128
#define WUm  192
#define SDL  (HDm*WDm)           // 6144
#define SPL  (HUm*WUm)           // 24576
#define ND   (BATCH*SDL)         // 12288
#define NP   (BATCH*SPL)         // 49152
#define KVP  640                 // kv0(256) | kv1(256) | ctxp(128)

typedef unsigned long long u64;

// ---------------- device scratch ------------------------------------------
__device__ float g_ctxln[ND*DI];
__device__ float g_x[NP*DI];
__device__ float g_kvp[ND*KVP];
__device__ float g_W[DI*KVP];
__device__ float g_bias[KVP];

// ---------------- packed f32x2 helpers ------------------------------------
__device__ __forceinline__ u64 fma2(u64 a, u64 b, u64 c) {
    u64 d;
    asm("fma.rn.f32x2 %0, %1, %2, %3;" : "=l"(d) : "l"(a), "l"(b), "l"(c));
    return d;
}
__device__ __forceinline__ float2 unpack2(u64 v) {
    float2 r;
    asm("mov.b64 {%0, %1}, %2;" : "=f"(r.x), "=f"(r.y) : "l"(v));
    return r;
}

// ========================================================================
// K1: fold nc_w/nc_b into combined weight
// ========================================================================
__global__ void prep_kernel(const float* __restrict__ nc_w,
                            const float* __restrict__ nc_b,
                            const float* __restrict__ wkv,
                            const float* __restrict__ bkv,
                            const float* __restrict__ wcf,
                            const float* __restrict__ bcf) {
    int j = blockIdx.x * blockDim.x + threadIdx.x;
    if (j >= KVP) return;
    if (j < 512) {
        int l  = j >> 8;
        int jj = j & 255;
        const float* w = wkv + (size_t)l * DI * 256;
        float bias = bkv[l*256 + jj];
        for (int c = 0; c < DI; c++) {
            float wv = w[c*256 + jj];
            g_W[c*KVP + j] = nc_w[l*DI + c] * wv;
            bias += nc_b[l*DI + c] * wv;
        }
        g_bias[j] = bias;
    } else {
        int jj = j - 512;
        for (int c = 0; c < DI; c++)
            g_W[c*KVP + j] = wcf[c*DI + jj];
        g_bias[j] = bcf[jj];
    }
}

// ========================================================================
// K2: transpose feat_map + fused LayerNorm
// ========================================================================
__global__ void trln_kernel(const float* __restrict__ fm) {
    __shared__ float st[DI][33];
    int dp0 = blockIdx.x * 32;
    int b = dp0 / SDL, hw0 = dp0 % SDL;
    const float* src = fm + (size_t)b * DI * SDL + hw0;
    int t = threadIdx.x;
    #pragma unroll
    for (int i = 0; i < 16; i++) {
        int e = t + i*256;
        int c = e >> 5, p = e & 31;
        st[c][p] = src[(size_t)c*SDL + p];
    }
    __syncthreads();
    int p = t >> 3, g = t & 7;
    float s = 0.f, s2 = 0.f;
    #pragma unroll
    for (int i = 0; i < 16; i++) {
        float v = st[g*16 + i][p];
        s += v; s2 += v*v;
    }
    #pragma unroll
    for (int off = 4; off; off >>= 1) {
        s  += __shfl_xor_sync(0xffffffffu, s,  off, 8);
        s2 += __shfl_xor_sync(0xffffffffu, s2, off, 8);
    }
    float mu   = s * (1.f/128.f);
    float rstd = rsqrtf(s2*(1.f/128.f) - mu*mu + 1e-6f);
    float* dst = g_ctxln + (size_t)(dp0 + p) * DI;
    #pragma unroll
    for (int i = 0; i < 16; i++) {
        int c = g*16 + i;
        dst[c] = (st[c][p] - mu) * rstd;
    }
}

// ========================================================================
// K3: transpose feat_map_up -> x rows
// ========================================================================
__global__ void trx_kernel(const float* __restrict__ fmu) {
    __shared__ float st[DI][33];
    int n0 = blockIdx.x * 32;
    int b = n0 / SPL, s0 = n0 % SPL;
    const float* src = fmu + (size_t)b * DI * SPL + s0;
    int t = threadIdx.x;
    #pragma unroll
    for (int i = 0; i < 16; i++) {
        int e = t + i*256;
        int c = e >> 5, p = e & 31;
        st[c][p] = src[(size_t)c*SPL + p];
    }
    __syncthreads();
    int p = t >> 3, g = t & 7;
    float* dst = g_x + (size_t)(n0 + p) * DI;
    #pragma unroll
    for (int i = 0; i < 16; i++) {
        int c = g*16 + i;
        dst[c] = st[c][p];
    }
}

// ========================================================================
// shared GEMM machinery: A row-major [128][132], W k-pair-interleaved
//   sW[k2*132 + j*2 + (k&1)] for a 64-column chunk, k2 = k/2
// thread (tx=t&15, ty=t>>4) owns rows ty*8..+7, cols tx*4..+3 (of chunk)
// ========================================================================
template<int K>
__device__ __forceinline__ void loadW(float* sW, const float* __restrict__ src,
                                      int ldw, int t) {
    constexpr int TOT = (K/2) * 64;
    #pragma unroll
    for (int f = t; f < TOT; f += 256) {
        int k2 = f >> 6, j = f & 63;
        const float* p = src + (size_t)(2*k2) * ldw + j;
        float2 v;
        v.x = __ldg(p);
        v.y = __ldg(p + ldw);
        *(float2*)(sW + k2*132 + j*2) = v;
    }
}

template<int K2>
__device__ __forceinline__ void gemm_core(const float* __restrict__ sA,
                                          const float* __restrict__ sW,
                                          u64 acc[8][4], int r0, int tx) {
    #pragma unroll 4
    for (int k2 = 0; k2 < K2; k2++) {
        u64 a[8];
        #pragma unroll
        for (int i = 0; i < 8; i++)
            a[i] = *(const u64*)(sA + (r0 + i)*132 + k2*2);
        const float* wp = sW + k2*132 + tx*8;
        ulonglong2 w01 = *(const ulonglong2*)(wp);
        ulonglong2 w23 = *(const ulonglong2*)(wp + 4);
        u64 w[4] = {w01.x, w01.y, w23.x, w23.y};
        #pragma unroll
        for (int i = 0; i < 8; i++)
            #pragma unroll
            for (int j = 0; j < 4; j++)
                acc[i][j] = fma2(a[i], w[j], acc[i][j]);
    }
}

__device__ __forceinline__ float gelu_tanh(float v) {
    float u = 0.7978845608028654f * (v + 0.044715f * v * v * v);
    u = fminf(fmaxf(u, -15.f), 15.f);
    float e = __expf(-2.f * u);
    float th = (1.f - e) / (1.f + e);
    return 0.5f * v * (1.f + th);
}

// LayerNorm x-registers -> sIn   (rows ty*8..+7, cols c*64+tx*4..+3)
__device__ __forceinline__ void ln_rows(const float xr[2][8][4], float* sIn,
                                        int ty, int tx) {
    #pragma unroll
    for (int i = 0; i < 8; i++) {
        float s = 0.f, s2 = 0.f;
        #pragma unroll
        for (int c = 0; c < 2; c++)
            #pragma unroll
            for (int j = 0; j < 4; j++) {
                float v = xr[c][i][j];
                s += v; s2 += v*v;
            }
        #pragma unroll
        for (int off = 8; off; off >>= 1) {
            s  += __shfl_xor_sync(0xffffffffu, s,  off, 16);
            s2 += __shfl_xor_sync(0xffffffffu, s2, off, 16);
        }
        float mu   = s * (1.f/128.f);
        float rstd = rsqrtf(s2*(1.f/128.f) - mu*mu + 1e-6f);
        #pragma unroll
        for (int c = 0; c < 2; c++) {
            float4 o;
            o.x = (xr[c][i][0] - mu)*rstd;
            o.y = (xr[c][i][1] - mu)*rstd;
            o.z = (xr[c][i][2] - mu)*rstd;
            o.w = (xr[c][i][3] - mu)*rstd;
            *(float4*)(sIn + (ty*8 + i)*132 + c*64 + tx*4) = o;
        }
    }
}

// ========================================================================
// K4: per-dpixel GEMM  g_kvp = g_ctxln @ g_W + g_bias   (f32x2 engine)
// ========================================================================
#define DGEMM_SMEM ((128*132 + 64*132) * 4)
__global__ void __launch_bounds__(256, 1) dgemm_kernel() {
    extern __shared__ float sm[];
    float* sIn = sm;                // 128x132
    float* sW  = sm + 128*132;      // 64x132
    int t = threadIdx.x;
    int tx = t & 15, ty = t >> 4;
    int n0 = blockIdx.x * 128;

    #pragma unroll
    for (int i = 0; i < 16; i++) {
        int f = t + i*256;
        int r = f >> 5, j4 = f & 31;
        *(float4*)(sIn + r*132 + j4*4) =
            *(const float4*)(g_ctxln + (size_t)(n0 + r)*DI + j4*4);
    }
    __syncthreads();

    for (int c = 0; c < 10; c++) {
        loadW<128>(sW, g_W + c*64, KVP, t);
        __syncthreads();
        u64 acc[8][4] = {};
        gemm_core<64>(sIn, sW, acc, ty*8, tx);
        float4 b4 = *(const float4*)(g_bias + c*64 + tx*4);
        float bb[4] = {b4.x, b4.y, b4.z, b4.w};
        #pragma unroll
        for (int i = 0; i < 8; i++) {
            float4 o;
            float2 p0 = unpack2(acc[i][0]);
            float2 p1 = unpack2(acc[i][1]);
            float2 p2 = unpack2(acc[i][2]);
            float2 p3 = unpack2(acc[i][3]);
            o.x = p0.x + p0.y + bb[0];
            o.y = p1.x + p1.y + bb[1];
            o.z = p2.x + p2.y + bb[2];
            o.w = p3.x + p3.y + bb[3];
            *(float4*)(g_kvp + (size_t)(n0 + ty*8 + i)*KVP + c*64 + tx*4) = o;
        }
        __syncthreads();
    }
}

// ========================================================================
// K5: mega kernel — 128 pixels/block, x resident in registers
// ========================================================================
#define MEGA_SMEM ((2*128*132 + 64*132) * 4)
__global__ void __launch_bounds__(256, 1) mega_kernel(
    const float* __restrict__ wq,  const float* __restrict__ bq,
    const float* __restrict__ wo,  const float* __restrict__ bo,
    const float* __restrict__ w1,  const float* __restrict__ b1,
    const float* __restrict__ w2,  const float* __restrict__ b2,
    const float* __restrict__ wqf, const float* __restrict__ bqf,
    float* __restrict__ out)
{
    extern __shared__ float sm[];
    float* sIn  = sm;               // 128x132 : LN(x) (GEMM A)
    float* sOut = sm + 128*132;     // 128x132 : q / o / gelu(h) / xq / probs
    float* sW   = sm + 2*128*132;   // 64x132  : weight chunk (k-pair layout)

    const int t  = threadIdx.x;
    const int tx = t & 15, ty = t >> 4;
    const int r0 = ty * 8;
    const int n0 = blockIdx.x * 128;
    const int ap = t >> 1;          // attention pixel (2 threads / pixel)
    const int hg = t & 1;

    // neighbor dpixel indices for pixel ap
    int dpix[9];
    {
        int n  = n0 + ap;
        int b  = n / SPL, s = n % SPL;
        int hu = s / WUm, wu = s % WUm;
        int hd = hu >> 1, wd = wu >> 1;
        #pragma unroll
        for (int i = 0; i < 3; i++)
            #pragma unroll
            for (int j = 0; j < 3; j++) {
                int hs = min(max(hd - 1 + i, 0), HDm - 1);
                int ws = min(max(wd - 1 + j, 0), WDm - 1);
                dpix[i*3 + j] = b*SDL + hs*WDm + ws;
            }
    }

    // x tile in registers: rows r0..r0+7, cols c*64 + tx*4 ..+3
    float xr[2][8][4];
    #pragma unroll
    for (int c = 0; c < 2; c++)
        #pragma unroll
        for (int i = 0; i < 8; i++) {
            float4 v = *(const float4*)(g_x + (size_t)(n0 + r0 + i)*DI
                                        + c*64 + tx*4);
            xr[c][i][0] = v.x; xr[c][i][1] = v.y;
            xr[c][i][2] = v.z; xr[c][i][3] = v.w;
        }

    for (int l = 0; l < 2; l++) {
        // ---------------- q = LN(x) @ wq + bq  -> sOut ----------------
        ln_rows(xr, sIn, ty, tx);
        __syncthreads();
        #pragma unroll
        for (int oc = 0; oc < 2; oc++) {
            loadW<128>(sW, wq + (size_t)l*DI*DI + oc*64, DI, t);
            __syncthreads();
            u64 acc[8][4] = {};
            gemm_core<64>(sIn, sW, acc, r0, tx);
            float4 b4 = *(const float4*)(bq + l*DI + oc*64 + tx*4);
            float bb[4] = {b4.x, b4.y, b4.z, b4.w};
            #pragma unroll
            for (int i = 0; i < 8; i++)
                #pragma unroll
                for (int j = 0; j < 4; j++) {
                    float2 p = unpack2(acc[i][j]);
                    sOut[(r0+i)*132 + oc*64 + tx*4 + j] = p.x + p.y + bb[j];
                }
            __syncthreads();
        }

        // ---------------- attention: 2 heads per thread ----------------
        {
            #pragma unroll
            for (int hh = 0; hh < 2; hh++) {
                int h = hg*2 + hh;
                float* qrow = sOut + ap*132 + h*32;
                float4 q4[8];
                #pragma unroll
                for (int i4 = 0; i4 < 8; i4++)
                    q4[i4] = *(const float4*)(qrow + i4*4);
                float lo[9];
                float m = -1e30f;
                #pragma unroll
                for (int kk = 0; kk < 9; kk++) {
                    const float* kv = g_kvp + (size_t)dpix[kk]*KVP + l*256 + h*32;
                    float d = 0.f;
                    #pragma unroll
                    for (int i4 = 0; i4 < 8; i4++) {
                        float4 k4 = __ldg((const float4*)(kv + i4*4));
                        d += q4[i4].x*k4.x + q4[i4].y*k4.y
                           + q4[i4].z*k4.z + q4[i4].w*k4.w;
                    }
                    lo[kk] = d * 0.17677669529663687f;
                    m = fmaxf(m, lo[kk]);
                }
                float ssum = 0.f;
                #pragma unroll
                for (int kk = 0; kk < 9; kk++) {
                    lo[kk] = __expf(lo[kk] - m);
                    ssum += lo[kk];
                }
                float inv = 1.f / ssum;
                float4 o4[8] = {};
                #pragma unroll
                for (int kk = 0; kk < 9; kk++) {
                    float w = lo[kk] * inv;
                    const float* vv = g_kvp + (size_t)dpix[kk]*KVP
                                      + l*256 + 128 + h*32;
                    #pragma unroll
                    for (int i4 = 0; i4 < 8; i4++) {
                        float4 v = __ldg((const float4*)(vv + i4*4));
                        o4[i4].x += w*v.x; o4[i4].y += w*v.y;
                        o4[i4].z += w*v.z; o4[i4].w += w*v.w;
                    }
                }
                #pragma unroll
                for (int i4 = 0; i4 < 8; i4++)
                    *(float4*)(qrow + i4*4) = o4[i4];
            }
        }
        __syncthreads();

        // ---------------- x += o @ wo + bo ----------------
        #pragma unroll
        for (int oc = 0; oc < 2; oc++) {
            loadW<128>(sW, wo + (size_t)l*DI*DI + oc*64, DI, t);
            __syncthreads();
            u64 acc[8][4] = {};
            gemm_core<64>(sOut, sW, acc, r0, tx);
            float4 b4 = *(const float4*)(bo + l*DI + oc*64 + tx*4);
            float bb[4] = {b4.x, b4.y, b4.z, b4.w};
            #pragma unroll
            for (int i = 0; i < 8; i++)
                #pragma unroll
                for (int j = 0; j < 4; j++) {
                    float2 p = unpack2(acc[i][j]);
                    xr[oc][i][j] += p.x + p.y + bb[j];
                }
            __syncthreads();
        }

        // ---------------- MLP ----------------
        ln_rows(xr, sIn, ty, tx);
        __syncthreads();
        for (int hc = 0; hc < 8; hc++) {
            loadW<128>(sW, w1 + (size_t)l*DI*512 + hc*64, 512, t);
            __syncthreads();
            {
                u64 acc[8][4] = {};
                gemm_core<64>(sIn, sW, acc, r0, tx);
                float4 b4 = *(const float4*)(b1 + l*512 + hc*64 + tx*4);
                float bb[4] = {b4.x, b4.y, b4.z, b4.w};
                #pragma unroll
                for (int i = 0; i < 8; i++)
                    #pragma unroll
                    for (int j = 0; j < 4; j++) {
                        float2 p = unpack2(acc[i][j]);
                        sOut[(r0+i)*132 + tx*4 + j] =
                            gelu_tanh(p.x + p.y + bb[j]);
                    }
            }
            __syncthreads();
            #pragma unroll
            for (int oc = 0; oc < 2; oc++) {
                loadW<64>(sW, w2 + (size_t)l*512*DI + (size_t)hc*64*DI + oc*64,
                          DI, t);
                __syncthreads();
                u64 acc[8][4] = {};
                gemm_core<32>(sOut, sW, acc, r0, tx);
                #pragma unroll
                for (int i = 0; i < 8; i++)
                    #pragma unroll
                    for (int j = 0; j < 4; j++) {
                        float2 p = unpack2(acc[i][j]);
                        xr[oc][i][j] += p.x + p.y;
                    }
                __syncthreads();
            }
        }
        #pragma unroll
        for (int oc = 0; oc < 2; oc++) {
            float4 b4 = *(const float4*)(b2 + l*DI + oc*64 + tx*4);
            float bb[4] = {b4.x, b4.y, b4.z, b4.w};
            #pragma unroll
            for (int i = 0; i < 8; i++)
                #pragma unroll
                for (int j = 0; j < 4; j++)
                    xr[oc][i][j] += bb[j];
        }
    }

    // ---------------- final: xq = LN(x) @ wqf + bqf -> sOut ----------------
    ln_rows(xr, sIn, ty, tx);
    __syncthreads();
    #pragma unroll
    for (int oc = 0; oc < 2; oc++) {
        loadW<128>(sW, wqf + oc*64, DI, t);
        __syncthreads();
        u64 acc[8][4] = {};
        gemm_core<64>(sIn, sW, acc, r0, tx);
        float4 b4 = *(const float4*)(bqf + oc*64 + tx*4);
        float bb[4] = {b4.x, b4.y, b4.z, b4.w};
        #pragma unroll
        for (int i = 0; i < 8; i++)
            #pragma unroll
            for (int j = 0; j < 4; j++) {
                float2 p = unpack2(acc[i][j]);
                sOut[(r0+i)*132 + oc*64 + tx*4 + j] = p.x + p.y + bb[j];
            }
        __syncthreads();
    }

    // ---------------- logits + 9-way softmax ----------------
    {
        const float* qrow = sOut + ap*132 + hg*64;
        float lo[9];
        #pragma unroll
        for (int kk = 0; kk < 9; kk++) {
            const float* cp = g_kvp + (size_t)dpix[kk]*KVP + 512 + hg*64;
            float d = 0.f;
            #pragma unroll
            for (int i4 = 0; i4 < 16; i4++) {
                float4 c = __ldg((const float4*)(cp + i4*4));
                float4 q = *(const float4*)(qrow + i4*4);
                d += q.x*c.x + q.y*c.y + q.z*c.z + q.w*c.w;
            }
            lo[kk] = d;
        }
        #pragma unroll
        for (int kk = 0; kk < 9; kk++) {
            lo[kk] += __shfl_xor_sync(0xffffffffu, lo[kk], 1);
            lo[kk] *= 0.08838834764831845f;
        }
        float m = -1e30f;
        #pragma unroll
        for (int kk = 0; kk < 9; kk++) m = fmaxf(m, lo[kk]);
        float ssum = 0.f;
        #pragma unroll
        for (int kk = 0; kk < 9; kk++) {
            lo[kk] = __expf(lo[kk] - m);
            ssum += lo[kk];
        }
        float inv = 1.f / ssum;
        __syncthreads();                     // sIn free (wqf gemm done)
        if (hg == 0) {
            #pragma unroll
            for (int kk = 0; kk < 9; kk++)
                sIn[kk*132 + ap] = lo[kk] * inv;
        }
    }
    __syncthreads();

    // ---------------- coalesced output write ----------------
    {
        int b = n0 / SPL, s0 = n0 % SPL;
        #pragma unroll
        for (int i = 0; i < 5; i++) {
            int f = t + i*256;
            if (f < 9*128) {
                int kk = f >> 7, p = f & 127;
                out[(size_t)b*9*SPL + (size_t)kk*SPL + s0 + p] = sIn[kk*132 + p];
            }
        }
    }
}

// ========================================================================
extern "C" void kernel_launch(void* const* d_in, const int* in_sizes, int n_in,
                              void* d_out, int out_size) {
    const float* feat_map    = (const float*)d_in[0];
    const float* feat_map_up = (const float*)d_in[1];
    const float* nc_w = (const float*)d_in[2];
    const float* nc_b = (const float*)d_in[3];
    const float* wq   = (const float*)d_in[4];
    const float* bq   = (const float*)d_in[5];
    const float* wkv  = (const float*)d_in[6];
    const float* bkv  = (const float*)d_in[7];
    const float* wo   = (const float*)d_in[8];
    const float* bo   = (const float*)d_in[9];
    const float* w1   = (const float*)d_in[10];
    const float* b1   = (const float*)d_in[11];
    const float* w2   = (const float*)d_in[12];
    const float* b2   = (const float*)d_in[13];
    const float* wqf  = (const float*)d_in[14];
    const float* bqf  = (const float*)d_in[15];
    const float* wcf  = (const float*)d_in[16];
    const float* bcf  = (const float*)d_in[17];
    float* out = (float*)d_out;

    cudaFuncSetAttribute(dgemm_kernel,
                         cudaFuncAttributeMaxDynamicSharedMemorySize, DGEMM_SMEM);
    cudaFuncSetAttribute(mega_kernel,
                         cudaFuncAttributeMaxDynamicSharedMemorySize, MEGA_SMEM);

    prep_kernel<<<3, 256>>>(nc_w, nc_b, wkv, bkv, wcf, bcf);
    trln_kernel<<<ND/32, 256>>>(feat_map);
    trx_kernel<<<NP/32, 256>>>(feat_map_up);
    dgemm_kernel<<<ND/128, 256, DGEMM_SMEM>>>();
    mega_kernel<<<NP/128, 256, MEGA_SMEM>>>(wq, bq, wo, bo, w1, b1, w2, b2,
                                            wqf, bqf, out);
}